// round 2
// baseline (speedup 1.0000x reference)
#include <cuda_runtime.h>
#include <cuda_bf16.h>
#include <cstdint>

// Problem constants (fixed shapes)
#define EDGES   100000
#define NSRC    10000
#define NDST    10000
#define CCH     128     // channels
#define K1      64      // MLP_IN
#define HID     128     // MLP_HID
#define WN      512     // W_NUMEL = 4*128
#define OUTC    2048    // C * SH_DIM

// Scratch (device globals: no allocation allowed)
__device__ float g_H[(size_t)EDGES * HID];     // 51.2 MB
__device__ float g_TPW[(size_t)EDGES * WN];    // 204.8 MB
__device__ float g_W1T[HID * K1];              // W1^T * (1/sqrt(64))
__device__ float g_W2T[WN * HID];              // W2^T * (1/sqrt(128))

// ---------------------------------------------------------------------------
// Packed fp32x2 FMA (ptxas never auto-generates FFMA2; PTX fma.rn.f32x2 does)
// ---------------------------------------------------------------------------
__device__ __forceinline__ void ffma2(unsigned long long& d,
                                      unsigned long long a,
                                      unsigned long long b) {
    asm("fma.rn.f32x2 %0, %1, %2, %0;" : "+l"(d) : "l"(a), "l"(b));
}

// ---------------------------------------------------------------------------
// Prep: transpose + prescale weights so GEMM smem fills are coalesced and
// K-pairing gets natural 8B-aligned LDS.64 on both operands.
// ---------------------------------------------------------------------------
__global__ void prep_w_kernel(const float* __restrict__ W1,
                              const float* __restrict__ W2) {
    int i = blockIdx.x * blockDim.x + threadIdx.x;
    if (i < K1 * HID) {
        int k = i / HID, n = i % HID;
        g_W1T[n * K1 + k] = W1[i] * 0.125f;               // 1/sqrt(64)
    }
    int j = i - K1 * HID;
    if (j >= 0 && j < HID * WN) {
        int k = j / WN, n = j % WN;
        g_W2T[n * HID + k] = W2[j] * 0.08838834764831843f; // 1/sqrt(128)
    }
}

// ---------------------------------------------------------------------------
// Tiled fp32 GEMM: C[m][n] = sum_k A[m][k] * BT[n][k]
// BM=BN=128, KC=32 chunks, 256 threads, 8x8 micro-tile per thread.
// K-paired accumulation in f32x2 (acc holds two partial sums, summed at end).
// Lane->column map n = tx + 16*j (bank stride 2 with pad 34 -> conflict-free).
// ---------------------------------------------------------------------------
template <int K, bool SILU>
__global__ void __launch_bounds__(256, 1)
gemm_kernel(const float* __restrict__ A, const float* __restrict__ BT,
            float* __restrict__ Cout, int N) {
    __shared__ float As[128][34];
    __shared__ float Bs[128][34];

    const int m0 = blockIdx.x * 128;
    const int n0 = blockIdx.y * 128;
    const int tid = threadIdx.x;
    const int tx = tid & 15;
    const int ty = tid >> 4;

    unsigned long long acc[8][8];
#pragma unroll
    for (int i = 0; i < 8; i++)
#pragma unroll
        for (int j = 0; j < 8; j++) acc[i][j] = 0ULL;

    for (int kk = 0; kk < K; kk += 32) {
        // Load A tile: 128 rows x 32 cols (float4 gmem, float2 smem stores)
#pragma unroll
        for (int i = tid; i < 1024; i += 256) {
            int r = i >> 3, c4 = i & 7;
            int gm = m0 + r;
            float4 v = make_float4(0.f, 0.f, 0.f, 0.f);
            if (gm < EDGES)
                v = *(const float4*)(A + (size_t)gm * K + kk + c4 * 4);
            *(float2*)&As[r][c4 * 4]     = make_float2(v.x, v.y);
            *(float2*)&As[r][c4 * 4 + 2] = make_float2(v.z, v.w);
        }
        // Load B tile: 128 rows (n) x 32 cols (k)
#pragma unroll
        for (int i = tid; i < 1024; i += 256) {
            int r = i >> 3, c4 = i & 7;
            float4 v = *(const float4*)(BT + (size_t)(n0 + r) * K + kk + c4 * 4);
            *(float2*)&Bs[r][c4 * 4]     = make_float2(v.x, v.y);
            *(float2*)&Bs[r][c4 * 4 + 2] = make_float2(v.z, v.w);
        }
        __syncthreads();

#pragma unroll
        for (int k2 = 0; k2 < 16; k2++) {
            unsigned long long ap[8], bp[8];
#pragma unroll
            for (int i = 0; i < 8; i++)
                ap[i] = *(const unsigned long long*)&As[ty + 16 * i][2 * k2];
#pragma unroll
            for (int j = 0; j < 8; j++)
                bp[j] = *(const unsigned long long*)&Bs[tx + 16 * j][2 * k2];
#pragma unroll
            for (int i = 0; i < 8; i++)
#pragma unroll
                for (int j = 0; j < 8; j++) ffma2(acc[i][j], ap[i], bp[j]);
        }
        __syncthreads();
    }

    // Epilogue: combine the two k-parity partial sums, optional silu, store.
#pragma unroll
    for (int i = 0; i < 8; i++) {
        int gm = m0 + ty + 16 * i;
        if (gm < EDGES) {
#pragma unroll
            for (int j = 0; j < 8; j++) {
                unsigned int lo = (unsigned int)acc[i][j];
                unsigned int hi = (unsigned int)(acc[i][j] >> 32);
                float v = __uint_as_float(lo) + __uint_as_float(hi);
                if (SILU) v = v / (1.0f + __expf(-v));
                Cout[(size_t)gm * N + n0 + tx + 16 * j] = v;
            }
        }
    }
}

// ---------------------------------------------------------------------------
// Tensor product + scatter-add. Warp per edge, 8 edges per 256-thread block.
// Output row layout: for l with degree d and base offset, pos = base + c*d + m.
// l-block boundaries (128, 512, 1152) are multiples of 32 so each warp
// iteration has a uniform l; c,m via magic-multiply division.
// ---------------------------------------------------------------------------
__global__ void __launch_bounds__(256)
tp_scatter_kernel(const float* __restrict__ TPW, const float* __restrict__ X,
                  const float* __restrict__ SH, const int* __restrict__ src,
                  const int* __restrict__ dst, float* __restrict__ out) {
    __shared__ __align__(16) float s_tpw[8][512];
    __shared__ __align__(16) float s_xs[8][128];
    __shared__ float s_sh[8][16];

    const int tid  = threadIdx.x;
    const int w    = tid >> 5;
    const int lane = tid & 31;
    const int e    = blockIdx.x * 8 + w;   // grid = EDGES/8 exactly

    const int s_idx = src[e];
    const int d_idx = dst[e];

    // Stage per-edge operands in shared memory (coalesced float4)
    const float4* tp4 = (const float4*)(TPW + (size_t)e * 512);
    float4* st4 = (float4*)s_tpw[w];
#pragma unroll
    for (int i = 0; i < 4; i++) st4[lane + 32 * i] = tp4[lane + 32 * i];

    ((float4*)s_xs[w])[lane] = ((const float4*)(X + (size_t)s_idx * 128))[lane];
    if (lane < 16) s_sh[w][lane] = SH[(size_t)e * 16 + lane];
    __syncwarp();

    float* orow = out + (size_t)d_idx * OUTC;
    const float* tw = s_tpw[w];
    const float* xs = s_xs[w];
    const float* sh = s_sh[w];

    // l=0 (d=1, base 0, tp_w block 0)
    {
        float sh0 = sh[0];
#pragma unroll
        for (int it = 0; it < 4; it++) {
            int c = it * 32 + lane;
            atomicAdd(orow + c, tw[c] * xs[c] * sh0);
        }
    }
    // l=1 (d=3, base 128, tp_w block 128, sh off 1)
#pragma unroll
    for (int it = 0; it < 12; it++) {
        int pp = it * 32 + lane;
        int c = (pp * 21846) >> 16;
        int m = pp - c * 3;
        atomicAdd(orow + 128 + pp, tw[128 + c] * xs[c] * sh[1 + m]);
    }
    // l=2 (d=5, base 512, tp_w block 256, sh off 4)
#pragma unroll
    for (int it = 0; it < 20; it++) {
        int pp = it * 32 + lane;
        int c = (pp * 13108) >> 16;
        int m = pp - c * 5;
        atomicAdd(orow + 512 + pp, tw[256 + c] * xs[c] * sh[4 + m]);
    }
    // l=3 (d=7, base 1152, tp_w block 384, sh off 9)
#pragma unroll
    for (int it = 0; it < 28; it++) {
        int pp = it * 32 + lane;
        int c = (pp * 9363) >> 16;
        int m = pp - c * 7;
        atomicAdd(orow + 1152 + pp, tw[384 + c] * xs[c] * sh[9 + m]);
    }
}

// ---------------------------------------------------------------------------
// Launch
// ---------------------------------------------------------------------------
extern "C" void kernel_launch(void* const* d_in, const int* in_sizes, int n_in,
                              void* d_out, int out_size) {
    const float* src_features = (const float*)d_in[0];
    const float* edge_sh      = (const float*)d_in[1];
    const float* edge_emb     = (const float*)d_in[2];
    const float* W1           = (const float*)d_in[3];
    const float* W2           = (const float*)d_in[4];
    const int*   src          = (const int*)d_in[5];
    const int*   dst          = (const int*)d_in[6];
    float*       out          = (float*)d_out;

    float *pH, *pTPW, *pW1T, *pW2T;
    cudaGetSymbolAddress((void**)&pH,   g_H);
    cudaGetSymbolAddress((void**)&pTPW, g_TPW);
    cudaGetSymbolAddress((void**)&pW1T, g_W1T);
    cudaGetSymbolAddress((void**)&pW2T, g_W2T);

    // Zero output (memset node in the graph)
    cudaMemsetAsync(out, 0, (size_t)NDST * OUTC * sizeof(float));

    // Transpose + prescale weights
    prep_w_kernel<<<(K1 * HID + HID * WN + 255) / 256, 256>>>(W1, W2);

    // GEMM1 + silu: H[E][128] = silu(edge_emb @ W1/sqrt(64))
    gemm_kernel<64, true><<<dim3((EDGES + 127) / 128, 1), 256>>>(
        edge_emb, pW1T, pH, HID);

    // GEMM2: TPW[E][512] = H @ W2/sqrt(128)
    gemm_kernel<128, false><<<dim3((EDGES + 127) / 128, 4), 256>>>(
        pH, pW2T, pTPW, WN);

    // Tensor product + scatter-add
    tp_scatter_kernel<<<EDGES / 8, 256>>>(pTPW, src_features, edge_sh,
                                          src, dst, out);
}

// round 5
// speedup vs baseline: 1.2927x; 1.2927x over previous
#include <cuda_runtime.h>
#include <cuda_bf16.h>
#include <cstdint>

// Problem constants (fixed shapes)
#define EDGES   100000
#define NSRC    10000
#define NDST    10000
#define CCH     128     // channels
#define K1      64      // MLP_IN
#define HID     128     // MLP_HID
#define WN      512     // W_NUMEL = 4*128
#define OUTC    2048    // C * SH_DIM

// Scratch (device globals: no allocation allowed)
__device__ __nv_bfloat16 g_Hh[(size_t)EDGES * HID];   // 25.6 MB  H hi (bf16 split)
__device__ __nv_bfloat16 g_Hl[(size_t)EDGES * HID];   // 25.6 MB  H lo
__device__ float         g_TPW[(size_t)EDGES * WN];   // 204.8 MB
__device__ float         g_W1T[HID * K1];             // W1^T * (1/sqrt(64))
__device__ __nv_bfloat16 g_W2Th[WN * HID];            // W2^T hi, prescaled
__device__ __nv_bfloat16 g_W2Tl[WN * HID];            // W2^T lo

// ---------------------------------------------------------------------------
// PTX helpers (family-compatible only: FFMA2, ldmatrix, mma.sync)
// ---------------------------------------------------------------------------
__device__ __forceinline__ void ffma2(unsigned long long& d,
                                      unsigned long long a,
                                      unsigned long long b) {
    asm("fma.rn.f32x2 %0, %1, %2, %0;" : "+l"(d) : "l"(a), "l"(b));
}

__device__ __forceinline__ uint32_t smem_u32(const void* p) {
    uint32_t a;
    asm("{ .reg .u64 t; cvta.to.shared.u64 t, %1; cvt.u32.u64 %0, t; }"
        : "=r"(a) : "l"(p));
    return a;
}

__device__ __forceinline__ void ldsm4(uint32_t* r, uint32_t addr) {
    asm volatile("ldmatrix.sync.aligned.m8n8.x4.shared.b16 {%0,%1,%2,%3}, [%4];"
                 : "=r"(r[0]), "=r"(r[1]), "=r"(r[2]), "=r"(r[3]) : "r"(addr));
}

__device__ __forceinline__ void mma_bf16(float* c, const uint32_t* a,
                                         const uint32_t* b) {
    asm volatile(
        "mma.sync.aligned.m16n8k16.row.col.f32.bf16.bf16.f32 "
        "{%0,%1,%2,%3}, {%4,%5,%6,%7}, {%8,%9}, {%0,%1,%2,%3};"
        : "+f"(c[0]), "+f"(c[1]), "+f"(c[2]), "+f"(c[3])
        : "r"(a[0]), "r"(a[1]), "r"(a[2]), "r"(a[3]), "r"(b[0]), "r"(b[1]));
}

// ---------------------------------------------------------------------------
// Prep: transpose + prescale weights. W1 stays fp32 (FFMA2 GEMM1); W2 is
// split into bf16 hi/lo pairs for the mma.sync GEMM2.
// ---------------------------------------------------------------------------
__global__ void prep_w_kernel(const float* __restrict__ W1,
                              const float* __restrict__ W2) {
    int i = blockIdx.x * blockDim.x + threadIdx.x;
    if (i < K1 * HID) {
        int k = i / HID, n = i % HID;
        g_W1T[n * K1 + k] = W1[i] * 0.125f;               // 1/sqrt(64)
    }
    int j = i - K1 * HID;
    if (j >= 0 && j < HID * WN) {
        int k = j / WN, n = j % WN;
        float v = W2[j] * 0.08838834764831843f;           // 1/sqrt(128)
        __nv_bfloat16 h = __float2bfloat16_rn(v);
        g_W2Th[n * HID + k] = h;
        g_W2Tl[n * HID + k] = __float2bfloat16_rn(v - __bfloat162float(h));
    }
}

// ---------------------------------------------------------------------------
// GEMM1 (fp32 FFMA2): H = silu(edge_emb @ W1s), emitted as bf16 hi/lo split.
// ---------------------------------------------------------------------------
__global__ void __launch_bounds__(256, 1)
gemm1_kernel(const float* __restrict__ A, const float* __restrict__ BT,
             __nv_bfloat16* __restrict__ OH, __nv_bfloat16* __restrict__ OL) {
    __shared__ float As[128][34];
    __shared__ float Bs[128][34];

    const int m0 = blockIdx.x * 128;
    const int tid = threadIdx.x;
    const int tx = tid & 15;
    const int ty = tid >> 4;

    unsigned long long acc[8][8];
#pragma unroll
    for (int i = 0; i < 8; i++)
#pragma unroll
        for (int j = 0; j < 8; j++) acc[i][j] = 0ULL;

    for (int kk = 0; kk < 64; kk += 32) {
#pragma unroll
        for (int i = tid; i < 1024; i += 256) {
            int r = i >> 3, c4 = i & 7;
            int gm = m0 + r;
            float4 v = make_float4(0.f, 0.f, 0.f, 0.f);
            if (gm < EDGES)
                v = *(const float4*)(A + (size_t)gm * 64 + kk + c4 * 4);
            *(float2*)&As[r][c4 * 4]     = make_float2(v.x, v.y);
            *(float2*)&As[r][c4 * 4 + 2] = make_float2(v.z, v.w);
        }
#pragma unroll
        for (int i = tid; i < 1024; i += 256) {
            int r = i >> 3, c4 = i & 7;
            float4 v = *(const float4*)(BT + (size_t)r * 64 + kk + c4 * 4);
            *(float2*)&Bs[r][c4 * 4]     = make_float2(v.x, v.y);
            *(float2*)&Bs[r][c4 * 4 + 2] = make_float2(v.z, v.w);
        }
        __syncthreads();

#pragma unroll
        for (int k2 = 0; k2 < 16; k2++) {
            unsigned long long ap[8], bp[8];
#pragma unroll
            for (int i = 0; i < 8; i++)
                ap[i] = *(const unsigned long long*)&As[ty + 16 * i][2 * k2];
#pragma unroll
            for (int j = 0; j < 8; j++)
                bp[j] = *(const unsigned long long*)&Bs[tx + 16 * j][2 * k2];
#pragma unroll
            for (int i = 0; i < 8; i++)
#pragma unroll
                for (int j = 0; j < 8; j++) ffma2(acc[i][j], ap[i], bp[j]);
        }
        __syncthreads();
    }

#pragma unroll
    for (int i = 0; i < 8; i++) {
        int gm = m0 + ty + 16 * i;
        if (gm < EDGES) {
#pragma unroll
            for (int j = 0; j < 8; j++) {
                unsigned int lo = (unsigned int)acc[i][j];
                unsigned int hi = (unsigned int)(acc[i][j] >> 32);
                float v = __uint_as_float(lo) + __uint_as_float(hi);
                v = v / (1.0f + __expf(-v));                 // silu
                __nv_bfloat16 h = __float2bfloat16_rn(v);
                size_t o = (size_t)gm * 128 + tx + 16 * j;
                OH[o] = h;
                OL[o] = __float2bfloat16_rn(v - __bfloat162float(h));
            }
        }
    }
}

// ---------------------------------------------------------------------------
// GEMM2 (mma.sync bf16 split-precision):
//   TPW[e][n] = sum_k (Hh+Hl)[e][k] * (Wh+Wl)[n][k]   (Hl*Wl dropped)
// CTA tile 128x128, full K=128 staged once. 8 warps (4M x 2N), warp tile
// 32x64, m16n8k16 fragments via ldmatrix.x4 from padded smem (stride 272B).
// Grid = (N/128=4, ceil(E/128)) so same-M CTAs share A through L2.
// ---------------------------------------------------------------------------
#define PAD     136                       // 128 + 8 bf16 -> 272B row stride
#define TILE_B  (128 * PAD * 2)           // 34816 bytes per bf16 tile
#define SM_AH   0
#define SM_AL   (TILE_B)
#define SM_BH   (2 * TILE_B)
#define SM_BL   (3 * TILE_B)
#define SM2_TOTAL (4 * TILE_B)            // 139264 bytes

__global__ void __launch_bounds__(256, 1)
gemm2_mma_kernel(const __nv_bfloat16* __restrict__ Ah,
                 const __nv_bfloat16* __restrict__ Al,
                 const __nv_bfloat16* __restrict__ Bh,
                 const __nv_bfloat16* __restrict__ Bl,
                 float* __restrict__ Cout) {
    extern __shared__ char smem[];
    const uint32_t sbase = smem_u32(smem);
    const int tid  = threadIdx.x;
    const int wid  = tid >> 5;
    const int lane = tid & 31;
    const int n0   = blockIdx.x * 128;
    const int m0   = blockIdx.y * 128;

    // ---- Stage A (hi+lo) and B (hi+lo), 16B per thread-iter, zero-padded A
    for (int q = tid; q < 2048; q += 256) {
        int r = q >> 4, c = q & 15;                  // row, 16B chunk
        uint32_t so = (uint32_t)r * 272 + (uint32_t)c * 16;
        int gm = m0 + r;
        uint4 vh = make_uint4(0, 0, 0, 0), vl = vh;
        if (gm < EDGES) {
            vh = *(const uint4*)(Ah + (size_t)gm * 128 + c * 8);
            vl = *(const uint4*)(Al + (size_t)gm * 128 + c * 8);
        }
        *(uint4*)(smem + SM_AH + so) = vh;
        *(uint4*)(smem + SM_AL + so) = vl;
        size_t gb = (size_t)(n0 + r) * 128 + c * 8;
        *(uint4*)(smem + SM_BH + so) = *(const uint4*)(Bh + gb);
        *(uint4*)(smem + SM_BL + so) = *(const uint4*)(Bl + gb);
    }
    __syncthreads();

    const int wm = wid & 3;           // 0..3 -> M offset wm*32
    const int wn = wid >> 2;          // 0..1 -> N offset wn*64

    // Per-thread ldmatrix address components
    // A x4 tile group: row = base + (lane&15), kbyte += (lane>>4)*16
    const uint32_t a_row  = (uint32_t)(wm * 32 + (lane & 15));
    const uint32_t a_kof  = (uint32_t)((lane >> 4) * 16);
    // B x4 (two n8 tiles): row = nb + (lane&7) + (lane>>4)*8,
    //                      kbyte += ((lane>>3)&1)*16
    const uint32_t b_row  = (uint32_t)(wn * 64 + (lane & 7) + (lane >> 4) * 8);
    const uint32_t b_kof  = (uint32_t)(((lane >> 3) & 1) * 16);

    float acc[2][8][4];
#pragma unroll
    for (int i = 0; i < 2; i++)
#pragma unroll
        for (int j = 0; j < 8; j++)
#pragma unroll
            for (int v = 0; v < 4; v++) acc[i][j][v] = 0.f;

    // Split-precision passes: (Ah,Bh), (Ah,Bl), (Al,Bh)
#pragma unroll
    for (int p = 0; p < 3; p++) {
        const uint32_t abase = sbase + ((p == 2) ? SM_AL : SM_AH);
        const uint32_t bbase = sbase + ((p == 1) ? SM_BL : SM_BH);
        const uint32_t aaddr0 = abase + a_row * 272 + a_kof;
        const uint32_t baddr0 = bbase + b_row * 272 + b_kof;

#pragma unroll
        for (int ks = 0; ks < 8; ks++) {
            uint32_t afr[2][4], bfr[4][4];
#pragma unroll
            for (int mt = 0; mt < 2; mt++)
                ldsm4(afr[mt], aaddr0 + (uint32_t)(mt * 16) * 272 + ks * 32);
#pragma unroll
            for (int np = 0; np < 4; np++)
                ldsm4(bfr[np], baddr0 + (uint32_t)(np * 16) * 272 + ks * 32);
#pragma unroll
            for (int mt = 0; mt < 2; mt++)
#pragma unroll
                for (int nt = 0; nt < 8; nt++)
                    mma_bf16(acc[mt][nt], afr[mt], &bfr[nt >> 1][(nt & 1) * 2]);
        }
    }

    // ---- Epilogue: float2 stores, full 32B sectors per thread-quad
    const int er0 = m0 + wm * 32 + (lane >> 2);
    const int ec0 = n0 + wn * 64 + 2 * (lane & 3);
#pragma unroll
    for (int mt = 0; mt < 2; mt++) {
        int r0 = er0 + mt * 16;
#pragma unroll
        for (int nt = 0; nt < 8; nt++) {
            int c = ec0 + nt * 8;
            if (r0 < EDGES)
                *(float2*)(Cout + (size_t)r0 * 512 + c) =
                    make_float2(acc[mt][nt][0], acc[mt][nt][1]);
            if (r0 + 8 < EDGES)
                *(float2*)(Cout + (size_t)(r0 + 8) * 512 + c) =
                    make_float2(acc[mt][nt][2], acc[mt][nt][3]);
        }
    }
}

// ---------------------------------------------------------------------------
// Tensor product + scatter-add (unchanged; next round's target).
// ---------------------------------------------------------------------------
__global__ void __launch_bounds__(256)
tp_scatter_kernel(const float* __restrict__ TPW, const float* __restrict__ X,
                  const float* __restrict__ SH, const int* __restrict__ src,
                  const int* __restrict__ dst, float* __restrict__ out) {
    __shared__ __align__(16) float s_tpw[8][512];
    __shared__ __align__(16) float s_xs[8][128];
    __shared__ float s_sh[8][16];

    const int tid  = threadIdx.x;
    const int w    = tid >> 5;
    const int lane = tid & 31;
    const int e    = blockIdx.x * 8 + w;   // grid = EDGES/8 exactly

    const int s_idx = src[e];
    const int d_idx = dst[e];

    const float4* tp4 = (const float4*)(TPW + (size_t)e * 512);
    float4* st4 = (float4*)s_tpw[w];
#pragma unroll
    for (int i = 0; i < 4; i++) st4[lane + 32 * i] = tp4[lane + 32 * i];

    ((float4*)s_xs[w])[lane] = ((const float4*)(X + (size_t)s_idx * 128))[lane];
    if (lane < 16) s_sh[w][lane] = SH[(size_t)e * 16 + lane];
    __syncwarp();

    float* orow = out + (size_t)d_idx * OUTC;
    const float* tw = s_tpw[w];
    const float* xs = s_xs[w];
    const float* sh = s_sh[w];

    {
        float sh0 = sh[0];
#pragma unroll
        for (int it = 0; it < 4; it++) {
            int c = it * 32 + lane;
            atomicAdd(orow + c, tw[c] * xs[c] * sh0);
        }
    }
#pragma unroll
    for (int it = 0; it < 12; it++) {
        int pp = it * 32 + lane;
        int c = (pp * 21846) >> 16;
        int m = pp - c * 3;
        atomicAdd(orow + 128 + pp, tw[128 + c] * xs[c] * sh[1 + m]);
    }
#pragma unroll
    for (int it = 0; it < 20; it++) {
        int pp = it * 32 + lane;
        int c = (pp * 13108) >> 16;
        int m = pp - c * 5;
        atomicAdd(orow + 512 + pp, tw[256 + c] * xs[c] * sh[4 + m]);
    }
#pragma unroll
    for (int it = 0; it < 28; it++) {
        int pp = it * 32 + lane;
        int c = (pp * 9363) >> 16;
        int m = pp - c * 7;
        atomicAdd(orow + 1152 + pp, tw[384 + c] * xs[c] * sh[9 + m]);
    }
}

// ---------------------------------------------------------------------------
// Launch
// ---------------------------------------------------------------------------
extern "C" void kernel_launch(void* const* d_in, const int* in_sizes, int n_in,
                              void* d_out, int out_size) {
    const float* src_features = (const float*)d_in[0];
    const float* edge_sh      = (const float*)d_in[1];
    const float* edge_emb     = (const float*)d_in[2];
    const float* W1           = (const float*)d_in[3];
    const float* W2           = (const float*)d_in[4];
    const int*   src          = (const int*)d_in[5];
    const int*   dst          = (const int*)d_in[6];
    float*       out          = (float*)d_out;

    __nv_bfloat16 *pHh, *pHl, *pW2Th, *pW2Tl;
    float *pTPW, *pW1T;
    cudaGetSymbolAddress((void**)&pHh,   g_Hh);
    cudaGetSymbolAddress((void**)&pHl,   g_Hl);
    cudaGetSymbolAddress((void**)&pTPW,  g_TPW);
    cudaGetSymbolAddress((void**)&pW1T,  g_W1T);
    cudaGetSymbolAddress((void**)&pW2Th, g_W2Th);
    cudaGetSymbolAddress((void**)&pW2Tl, g_W2Tl);

    cudaFuncSetAttribute(gemm2_mma_kernel,
                         cudaFuncAttributeMaxDynamicSharedMemorySize, SM2_TOTAL);

    // Zero output
    cudaMemsetAsync(out, 0, (size_t)NDST * OUTC * sizeof(float));

    // Transpose + prescale weights (W2 -> bf16 hi/lo split)
    prep_w_kernel<<<(K1 * HID + HID * WN + 255) / 256, 256>>>(W1, W2);

    // GEMM1 + silu -> bf16 split H
    gemm1_kernel<<<(EDGES + 127) / 128, 256>>>(edge_emb, pW1T, pHh, pHl);

    // GEMM2 on mma.sync tensor cores (split-precision bf16)
    gemm2_mma_kernel<<<dim3(4, (EDGES + 127) / 128), 256, SM2_TOTAL>>>(
        pHh, pHl, pW2Th, pW2Tl, pTPW);

    // Tensor product + scatter-add
    tp_scatter_kernel<<<EDGES / 8, 256>>>(pTPW, src_features, edge_sh,
                                          src, dst, out);
}